// round 3
// baseline (speedup 1.0000x reference)
#include <cuda_runtime.h>
#include <math.h>

// Problem dims
#define B_ 2
#define T_ 256
#define N_ 128
#define F_ 16
#define D_ 128
#define H_ 288
#define E_ 1024
#define M_TOTAL (B_*T_*N_)   // 65536 flattened node-time rows

// Chain kernel tiling
#define BM 128
#define LDA 132              // 128 + 4 pad
#define NTHREADS 512
#define WCHUNK (32*LDA)
#define CHAIN_SMEM ((2*BM*LDA + 2*WCHUNK) * sizeof(float))   // 168960 B

// Scratch (static device arrays: allocation-free per harness rules)
__device__ float g_S1[(size_t)M_TOTAL * H_];   // send @ Wc1[0:128,:]
__device__ float g_R1[(size_t)M_TOTAL * H_];   // recv @ Wc1[144:272,:]
__device__ float g_pet[255 * H_];              // pe terms + bc1

// ---------------------------------------------------------------------------
// load one 32xD weight chunk into smem [32][LDA] (512 threads, 2 float4 each)
// ---------------------------------------------------------------------------
__device__ __forceinline__ void load_w128(float* __restrict__ dst,
                                          const float* __restrict__ Wg,
                                          int kc, int tid)
{
    #pragma unroll
    for (int it = 0; it < 2; it++) {
        int l  = tid + it * NTHREADS;          // 0..1023
        int kk = l >> 5;
        int c4 = (l & 31) * 4;
        float4 v = *reinterpret_cast<const float4*>(Wg + (size_t)(kc + kk) * 128 + c4);
        float* d = dst + kk * LDA + c4;
        d[0] = v.x; d[1] = v.y; d[2] = v.z; d[3] = v.w;
    }
}

// load one 32x96 chunk of Wc1 (row stride H_=288) into smem [32][LDA]
__device__ __forceinline__ void load_w96(float* __restrict__ dst,
                                         const float* __restrict__ Wg,
                                         int kc, int col0, int tid)
{
    #pragma unroll
    for (int it = 0; it < 2; it++) {
        int l = tid + it * NTHREADS;           // 0..1023, need < 768
        if (l < 768) {
            int kk = l / 24;
            int c4 = (l % 24) * 4;
            float4 v = *reinterpret_cast<const float4*>(
                Wg + (size_t)(kc + kk) * H_ + col0 + c4);
            float* d = dst + kk * LDA + c4;
            d[0] = v.x; d[1] = v.y; d[2] = v.z; d[3] = v.w;
        }
    }
}

// ---------------------------------------------------------------------------
// mlp128: C = relu(A @ W + b). A,C smem [128][LDA], W global [128][128].
// 512 threads, 4x8 per-thread tile, double-buffered 32-row weight chunks.
// Caller must ensure a __syncthreads() separates prior reads of wb0 from here.
// ---------------------------------------------------------------------------
__device__ __forceinline__ void mlp128(const float* __restrict__ Asm,
                                       float* __restrict__ Csm,
                                       float* __restrict__ wb0,
                                       float* __restrict__ wb1,
                                       const float* __restrict__ Wg,
                                       const float* __restrict__ bg,
                                       int tid, int m0, int n0)
{
    float c[4][8] = {};
    float* cur = wb0;
    float* nxt = wb1;
    load_w128(cur, Wg, 0, tid);
    __syncthreads();
    #pragma unroll 1
    for (int ch = 0; ch < 4; ch++) {
        if (ch < 3) load_w128(nxt, Wg, (ch + 1) * 32, tid);
        const int kc = ch * 32;
        #pragma unroll
        for (int kk = 0; kk < 32; kk++) {
            float a[4], w[8];
            #pragma unroll
            for (int i = 0; i < 4; i++) a[i] = Asm[(m0 + i) * LDA + kc + kk];
            #pragma unroll
            for (int j = 0; j < 8; j++) w[j] = cur[kk * LDA + n0 + j];
            #pragma unroll
            for (int i = 0; i < 4; i++)
                #pragma unroll
                for (int j = 0; j < 8; j++)
                    c[i][j] = fmaf(a[i], w[j], c[i][j]);
        }
        __syncthreads();
        float* t = cur; cur = nxt; nxt = t;
    }
    float bb[8];
    #pragma unroll
    for (int j = 0; j < 8; j++) bb[j] = __ldg(bg + n0 + j);
    #pragma unroll
    for (int i = 0; i < 4; i++)
        #pragma unroll
        for (int j = 0; j < 8; j++)
            Csm[(m0 + i) * LDA + n0 + j] = fmaxf(c[i][j] + bb[j], 0.f);
}

// ---------------------------------------------------------------------------
// chain_kernel: per 128-row tile, fused
//   emb = spikes@W_emb + b_emb
//   h1  = relu(emb@W1 + b1)
//   s   = relu(h1@W2 + b2)
//   Out = s @ Wc1_sub (128 x 288; bc1 folded into g_pet)
// blockIdx.y: 0 = send chain -> g_S1, 1 = recv chain -> g_R1
// ---------------------------------------------------------------------------
__global__ __launch_bounds__(NTHREADS, 1)
void chain_kernel(const float* __restrict__ spikes,
                  const float* __restrict__ W_emb, const float* __restrict__ b_emb,
                  const float* __restrict__ Ws1, const float* __restrict__ bs1,
                  const float* __restrict__ Ws2, const float* __restrict__ bs2,
                  const float* __restrict__ Wr1, const float* __restrict__ br1,
                  const float* __restrict__ Wr2, const float* __restrict__ br2,
                  const float* __restrict__ Wc1)
{
    extern __shared__ float sm[];
    float* actA = sm;                       // [BM][LDA]
    float* actB = sm + BM * LDA;            // [BM][LDA]
    float* wb0  = sm + 2 * BM * LDA;        // [32][LDA]
    float* wb1  = wb0 + WCHUNK;             // [32][LDA]

    const int chain = blockIdx.y;
    const float* W1 = chain ? Wr1 : Ws1;
    const float* b1 = chain ? br1 : bs1;
    const float* W2 = chain ? Wr2 : Ws2;
    const float* b2 = chain ? br2 : bs2;
    const float* Wc = Wc1 + (chain ? 144 * H_ : 0);
    float* Out = chain ? g_R1 : g_S1;

    const int row0 = blockIdx.x * BM;
    const int tid  = threadIdx.x;
    const int tx   = tid & 15;              // 16 column groups
    const int ty   = tid >> 4;              // 32 row groups
    const int m0   = ty * 4;
    const int n0   = tx * 8;

    // ---- Step 0: emb = spikes @ W_emb + b_emb -> actA -------------------
    // spikes^T staged in wb0 rows 0..15 ([k][m]), W_emb in wb1 rows 0..15.
    {
        {
            int l = tid;                    // 0..511
            int m = l >> 2;
            int q = l & 3;
            float4 v = *reinterpret_cast<const float4*>(
                spikes + (size_t)(row0 + m) * F_ + q * 4);
            wb0[(q * 4 + 0) * LDA + m] = v.x;
            wb0[(q * 4 + 1) * LDA + m] = v.y;
            wb0[(q * 4 + 2) * LDA + m] = v.z;
            wb0[(q * 4 + 3) * LDA + m] = v.w;

            int k  = l >> 5;
            int c4 = (l & 31) * 4;
            float4 w = *reinterpret_cast<const float4*>(W_emb + k * 128 + c4);
            float* d = wb1 + k * LDA + c4;
            d[0] = w.x; d[1] = w.y; d[2] = w.z; d[3] = w.w;
        }
        __syncthreads();

        float c[4][8] = {};
        #pragma unroll
        for (int k = 0; k < 16; k++) {
            float a[4], w[8];
            #pragma unroll
            for (int i = 0; i < 4; i++) a[i] = wb0[k * LDA + m0 + i];
            #pragma unroll
            for (int j = 0; j < 8; j++) w[j] = wb1[k * LDA + n0 + j];
            #pragma unroll
            for (int i = 0; i < 4; i++)
                #pragma unroll
                for (int j = 0; j < 8; j++)
                    c[i][j] = fmaf(a[i], w[j], c[i][j]);
        }
        float bb[8];
        #pragma unroll
        for (int j = 0; j < 8; j++) bb[j] = __ldg(b_emb + n0 + j);
        #pragma unroll
        for (int i = 0; i < 4; i++)
            #pragma unroll
            for (int j = 0; j < 8; j++)
                actA[(m0 + i) * LDA + n0 + j] = c[i][j] + bb[j];
        __syncthreads();   // wb0/wb1 reads done before mlp128 prologue writes
    }

    // ---- Step 1: h1 = relu(emb @ W1 + b1) -> actB -----------------------
    mlp128(actA, actB, wb0, wb1, W1, b1, tid, m0, n0);
    // ---- Step 2: s = relu(h1 @ W2 + b2) -> actA -------------------------
    mlp128(actB, actA, wb0, wb1, W2, b2, tid, m0, n0);

    // ---- Step 3: Out = s @ Wc [128 x 288], 3 column chunks of 96 --------
    const int nc0 = tx * 6;
    #pragma unroll 1
    for (int c3 = 0; c3 < 3; c3++) {
        const int col0 = c3 * 96;
        float c[4][6] = {};
        float* cur = wb0;
        float* nxt = wb1;
        load_w96(cur, Wc, 0, col0, tid);
        __syncthreads();
        #pragma unroll 1
        for (int ch = 0; ch < 4; ch++) {
            if (ch < 3) load_w96(nxt, Wc, (ch + 1) * 32, col0, tid);
            const int kc = ch * 32;
            #pragma unroll
            for (int kk = 0; kk < 32; kk++) {
                float a[4], w[6];
                #pragma unroll
                for (int i = 0; i < 4; i++) a[i] = actA[(m0 + i) * LDA + kc + kk];
                #pragma unroll
                for (int j = 0; j < 6; j++) w[j] = cur[kk * LDA + nc0 + j];
                #pragma unroll
                for (int i = 0; i < 4; i++)
                    #pragma unroll
                    for (int j = 0; j < 6; j++)
                        c[i][j] = fmaf(a[i], w[j], c[i][j]);
            }
            __syncthreads();
            float* t = cur; cur = nxt; nxt = t;
        }
        #pragma unroll
        for (int i = 0; i < 4; i++) {
            float* op = Out + (size_t)(row0 + m0 + i) * H_ + col0 + nc0;
            #pragma unroll
            for (int j = 0; j < 6; j++) op[j] = c[i][j];
        }
    }
}

// ---------------------------------------------------------------------------
// pet_kernel: pet[t][c] = pe[t+1] @ Wc1[128:144,c] + pe[t] @ Wc1[272:288,c] + bc1[c]
// ---------------------------------------------------------------------------
__global__ void pet_kernel(const float* __restrict__ Wc1,
                           const float* __restrict__ bc1)
{
    const int t = blockIdx.x;       // 0..254
    const int c = threadIdx.x;      // 0..287

    __shared__ float sv[4][8];
    if (c < 8) {
        int i = c;
        double dv = exp((double)(2 * i) * (-log(10000.0) / 16.0));
        double a1 = (double)(t + 1) * dv;
        double a0 = (double)t * dv;
        sv[0][i] = (float)sin(a1);
        sv[1][i] = (float)cos(a1);
        sv[2][i] = (float)sin(a0);
        sv[3][i] = (float)cos(a0);
    }
    __syncthreads();

    float acc = bc1[c];
    #pragma unroll
    for (int i = 0; i < 8; i++) {
        acc = fmaf(sv[0][i], Wc1[(128 + 2 * i) * H_ + c], acc);
        acc = fmaf(sv[1][i], Wc1[(129 + 2 * i) * H_ + c], acc);
        acc = fmaf(sv[2][i], Wc1[(272 + 2 * i) * H_ + c], acc);
        acc = fmaf(sv[3][i], Wc1[(273 + 2 * i) * H_ + c], acc);
    }
    g_pet[t * H_ + c] = acc;
}

// ---------------------------------------------------------------------------
// edge_kernel: per (b,t) block:
//   h[e,k] = relu(S1[b,t+1,se[e],k] + R1[b,t,re[e],k] + pet[t,k])
//   out[b,t,e,:] = h[e,:] @ Wc2 + bc2
// ---------------------------------------------------------------------------
__global__ __launch_bounds__(256)
void edge_kernel(const int* __restrict__ se, const int* __restrict__ re,
                 const float* __restrict__ Wc2, const float* __restrict__ bc2,
                 float* __restrict__ out)
{
    __shared__ float sS[128][33];
    __shared__ float sR[128][33];
    __shared__ float sW[H_ * 5];
    __shared__ float sPet[H_];

    const int t   = blockIdx.x;     // 0..254
    const int b   = blockIdx.y;     // 0..1
    const int tid = threadIdx.x;

    const float* Srow = g_S1 + (size_t)((b * T_ + t + 1) * N_) * H_;
    const float* Rrow = g_R1 + (size_t)((b * T_ + t) * N_) * H_;

    for (int l = tid; l < H_ * 5; l += 256) sW[l] = Wc2[l];
    for (int l = tid; l < H_;     l += 256) sPet[l] = g_pet[t * H_ + l];

    float bb[5];
    #pragma unroll
    for (int j = 0; j < 5; j++) bb[j] = __ldg(bc2 + j);

    int es[4], er[4];
    #pragma unroll
    for (int u = 0; u < 4; u++) {
        int e = u * 256 + tid;
        es[u] = __ldg(se + e);
        er[u] = __ldg(re + e);
    }
    float acc[4][5] = {};

    #pragma unroll 1
    for (int kc = 0; kc < H_; kc += 32) {
        __syncthreads();
        #pragma unroll
        for (int it = 0; it < 4; it++) {
            int l  = tid + it * 256;     // 0..1023
            int n  = l >> 3;
            int k4 = (l & 7) * 4;
            float4 v = *reinterpret_cast<const float4*>(Srow + (size_t)n * H_ + kc + k4);
            sS[n][k4 + 0] = v.x; sS[n][k4 + 1] = v.y;
            sS[n][k4 + 2] = v.z; sS[n][k4 + 3] = v.w;
            float4 u4 = *reinterpret_cast<const float4*>(Rrow + (size_t)n * H_ + kc + k4);
            sR[n][k4 + 0] = u4.x; sR[n][k4 + 1] = u4.y;
            sR[n][k4 + 2] = u4.z; sR[n][k4 + 3] = u4.w;
        }
        __syncthreads();
        #pragma unroll
        for (int kk = 0; kk < 32; kk++) {
            float pv = sPet[kc + kk];
            float w0 = sW[(kc + kk) * 5 + 0];
            float w1 = sW[(kc + kk) * 5 + 1];
            float w2 = sW[(kc + kk) * 5 + 2];
            float w3 = sW[(kc + kk) * 5 + 3];
            float w4 = sW[(kc + kk) * 5 + 4];
            #pragma unroll
            for (int u = 0; u < 4; u++) {
                float h = sS[es[u]][kk] + sR[er[u]][kk] + pv;
                h = fmaxf(h, 0.f);
                acc[u][0] = fmaf(h, w0, acc[u][0]);
                acc[u][1] = fmaf(h, w1, acc[u][1]);
                acc[u][2] = fmaf(h, w2, acc[u][2]);
                acc[u][3] = fmaf(h, w3, acc[u][3]);
                acc[u][4] = fmaf(h, w4, acc[u][4]);
            }
        }
    }

    #pragma unroll
    for (int u = 0; u < 4; u++) {
        int e = u * 256 + tid;
        size_t o = ((size_t)(b * 255 + t) * E_ + e) * 5;
        #pragma unroll
        for (int j = 0; j < 5; j++) out[o + j] = acc[u][j] + bb[j];
    }
}

// ---------------------------------------------------------------------------
extern "C" void kernel_launch(void* const* d_in, const int* in_sizes, int n_in,
                              void* d_out, int out_size)
{
    const float* spikes = (const float*)d_in[0];
    const float* W_emb  = (const float*)d_in[1];
    const float* b_emb  = (const float*)d_in[2];
    const float* Ws1    = (const float*)d_in[3];
    const float* bs1    = (const float*)d_in[4];
    const float* Ws2    = (const float*)d_in[5];
    const float* bs2    = (const float*)d_in[6];
    const float* Wr1    = (const float*)d_in[7];
    const float* br1    = (const float*)d_in[8];
    const float* Wr2    = (const float*)d_in[9];
    const float* br2    = (const float*)d_in[10];
    const float* Wc1    = (const float*)d_in[11];
    const float* bc1    = (const float*)d_in[12];
    const float* Wc2    = (const float*)d_in[13];
    const float* bc2    = (const float*)d_in[14];
    const int*   se     = (const int*)d_in[15];
    const int*   re     = (const int*)d_in[16];
    float* out = (float*)d_out;

    cudaFuncSetAttribute(chain_kernel,
                         cudaFuncAttributeMaxDynamicSharedMemorySize,
                         (int)CHAIN_SMEM);

    chain_kernel<<<dim3(M_TOTAL / BM, 2), NTHREADS, CHAIN_SMEM>>>(
        spikes, W_emb, b_emb, Ws1, bs1, Ws2, bs2, Wr1, br1, Wr2, br2, Wc1);

    pet_kernel<<<255, H_>>>(Wc1, bc1);

    edge_kernel<<<dim3(255, 2), 256>>>(se, re, Wc2, bc2, out);
}

// round 4
// speedup vs baseline: 1.1742x; 1.1742x over previous
#include <cuda_runtime.h>
#include <math.h>

// Problem dims
#define B_ 2
#define T_ 256
#define N_ 128
#define F_ 16
#define D_ 128
#define H_ 288
#define E_ 1024
#define M_TOTAL (B_*T_*N_)

// Chain kernel tiling
#define BM 128
#define LDA 132              // 128 + 4 pad (floats)
#define NTHREADS 256
#define WCHUNK (32*LDA)
#define CHAIN_SMEM ((2*BM*LDA + 2*WCHUNK) * sizeof(float))   // 168960 B

__device__ float g_S1[(size_t)M_TOTAL * H_];
__device__ float g_R1[(size_t)M_TOTAL * H_];
__device__ float g_pet[255 * H_];

// ---------------------------------------------------------------------------
// load one 32x128 weight chunk into smem [32][LDA] (256 threads, 4 float4)
// ---------------------------------------------------------------------------
__device__ __forceinline__ void load_w128(float* __restrict__ dst,
                                          const float* __restrict__ Wg,
                                          int kc, int tid)
{
    #pragma unroll
    for (int it = 0; it < 4; it++) {
        int l  = tid + it * NTHREADS;          // 0..1023
        int kk = l >> 5;
        int c4 = (l & 31) * 4;
        float4 v = *reinterpret_cast<const float4*>(Wg + (size_t)(kc + kk) * 128 + c4);
        *reinterpret_cast<float4*>(dst + kk * LDA + c4) = v;
    }
}

// load one 32x96 chunk of Wc1 (row stride H_=288) into smem [32][LDA]
__device__ __forceinline__ void load_w96(float* __restrict__ dst,
                                         const float* __restrict__ Wg,
                                         int kc, int col0, int tid)
{
    #pragma unroll
    for (int it = 0; it < 3; it++) {
        int l  = tid + it * NTHREADS;          // 0..767
        int kk = l / 24;
        int c4 = (l % 24) * 4;
        float4 v = *reinterpret_cast<const float4*>(
            Wg + (size_t)(kc + kk) * H_ + col0 + c4);
        *reinterpret_cast<float4*>(dst + kk * LDA + c4) = v;
    }
}

// ---------------------------------------------------------------------------
// mlp128T: C^T = relu(A @ W + b)^T with A stored transposed.
//   Asm: [k][m]  (k=0..127 feature, m=0..127 row), stride LDA
//   Csm: [n][m]  (output feature-major), stride LDA
//   W global [128][128] row-major (k-major), staged in wb (double buffered).
// 256 threads, 8x8 per-thread tile, all smem accesses via float4.
// ---------------------------------------------------------------------------
__device__ __forceinline__ void mlp128T(const float* __restrict__ Asm,
                                        float* __restrict__ Csm,
                                        float* __restrict__ wb0,
                                        float* __restrict__ wb1,
                                        const float* __restrict__ Wg,
                                        const float* __restrict__ bg,
                                        int tid, int m0, int n0)
{
    float c[8][8] = {};
    float* cur = wb0;
    float* nxt = wb1;
    load_w128(cur, Wg, 0, tid);
    __syncthreads();
    #pragma unroll 1
    for (int ch = 0; ch < 4; ch++) {
        if (ch < 3) load_w128(nxt, Wg, (ch + 1) * 32, tid);
        const int kc = ch * 32;
        #pragma unroll 8
        for (int kk = 0; kk < 32; kk++) {
            float4 a0 = *reinterpret_cast<const float4*>(Asm + (kc + kk) * LDA + m0);
            float4 a1 = *reinterpret_cast<const float4*>(Asm + (kc + kk) * LDA + m0 + 4);
            float4 w0 = *reinterpret_cast<const float4*>(cur + kk * LDA + n0);
            float4 w1 = *reinterpret_cast<const float4*>(cur + kk * LDA + n0 + 4);
            float a[8] = {a0.x, a0.y, a0.z, a0.w, a1.x, a1.y, a1.z, a1.w};
            float w[8] = {w0.x, w0.y, w0.z, w0.w, w1.x, w1.y, w1.z, w1.w};
            #pragma unroll
            for (int i = 0; i < 8; i++)
                #pragma unroll
                for (int j = 0; j < 8; j++)
                    c[i][j] = fmaf(a[i], w[j], c[i][j]);
        }
        __syncthreads();
        float* t = cur; cur = nxt; nxt = t;
    }
    float bb[8];
    #pragma unroll
    for (int j = 0; j < 8; j++) bb[j] = __ldg(bg + n0 + j);
    #pragma unroll
    for (int j = 0; j < 8; j++) {
        float4 lo, hi;
        lo.x = fmaxf(c[0][j] + bb[j], 0.f);
        lo.y = fmaxf(c[1][j] + bb[j], 0.f);
        lo.z = fmaxf(c[2][j] + bb[j], 0.f);
        lo.w = fmaxf(c[3][j] + bb[j], 0.f);
        hi.x = fmaxf(c[4][j] + bb[j], 0.f);
        hi.y = fmaxf(c[5][j] + bb[j], 0.f);
        hi.z = fmaxf(c[6][j] + bb[j], 0.f);
        hi.w = fmaxf(c[7][j] + bb[j], 0.f);
        *reinterpret_cast<float4*>(Csm + (n0 + j) * LDA + m0)     = lo;
        *reinterpret_cast<float4*>(Csm + (n0 + j) * LDA + m0 + 4) = hi;
    }
}

// ---------------------------------------------------------------------------
// chain_kernel (transposed-activation variant)
// ---------------------------------------------------------------------------
__global__ __launch_bounds__(NTHREADS, 1)
void chain_kernel(const float* __restrict__ spikes,
                  const float* __restrict__ W_emb, const float* __restrict__ b_emb,
                  const float* __restrict__ Ws1, const float* __restrict__ bs1,
                  const float* __restrict__ Ws2, const float* __restrict__ bs2,
                  const float* __restrict__ Wr1, const float* __restrict__ br1,
                  const float* __restrict__ Wr2, const float* __restrict__ br2,
                  const float* __restrict__ Wc1)
{
    extern __shared__ float sm[];
    float* actA = sm;                       // [128][LDA] transposed act
    float* actB = sm + BM * LDA;            // [128][LDA]
    float* wb0  = sm + 2 * BM * LDA;
    float* wb1  = wb0 + WCHUNK;

    const int chain = blockIdx.y;
    const float* W1 = chain ? Wr1 : Ws1;
    const float* b1 = chain ? br1 : bs1;
    const float* W2 = chain ? Wr2 : Ws2;
    const float* b2 = chain ? br2 : bs2;
    const float* Wc = Wc1 + (chain ? 144 * H_ : 0);
    float* Out = chain ? g_R1 : g_S1;

    const int row0 = blockIdx.x * BM;
    const int tid  = threadIdx.x;
    const int tx   = tid & 15;
    const int ty   = tid >> 4;
    const int m0   = ty * 8;
    const int n0   = tx * 8;

    // ---- Step 0: embT = (spikes @ W_emb + b_emb)^T -> actA [n][m] -------
    // spikes^T staged in wb0 [f][m], W_emb in wb1 [f][n].
    {
        #pragma unroll
        for (int it = 0; it < 2; it++) {
            int l = tid * 2 + it;           // 0..511
            int m = l >> 2;
            int q = l & 3;
            float4 v = *reinterpret_cast<const float4*>(
                spikes + (size_t)(row0 + m) * F_ + q * 4);
            wb0[(q * 4 + 0) * LDA + m] = v.x;
            wb0[(q * 4 + 1) * LDA + m] = v.y;
            wb0[(q * 4 + 2) * LDA + m] = v.z;
            wb0[(q * 4 + 3) * LDA + m] = v.w;
        }
        #pragma unroll
        for (int it = 0; it < 2; it++) {
            int l  = tid * 2 + it;          // 0..511
            int k  = l >> 5;
            int c4 = (l & 31) * 4;
            float4 v = *reinterpret_cast<const float4*>(W_emb + k * 128 + c4);
            *reinterpret_cast<float4*>(wb1 + k * LDA + c4) = v;
        }
        __syncthreads();

        float c[8][8] = {};
        #pragma unroll
        for (int k = 0; k < 16; k++) {
            float4 a0 = *reinterpret_cast<const float4*>(wb0 + k * LDA + m0);
            float4 a1 = *reinterpret_cast<const float4*>(wb0 + k * LDA + m0 + 4);
            float4 w0 = *reinterpret_cast<const float4*>(wb1 + k * LDA + n0);
            float4 w1 = *reinterpret_cast<const float4*>(wb1 + k * LDA + n0 + 4);
            float a[8] = {a0.x, a0.y, a0.z, a0.w, a1.x, a1.y, a1.z, a1.w};
            float w[8] = {w0.x, w0.y, w0.z, w0.w, w1.x, w1.y, w1.z, w1.w};
            #pragma unroll
            for (int i = 0; i < 8; i++)
                #pragma unroll
                for (int j = 0; j < 8; j++)
                    c[i][j] = fmaf(a[i], w[j], c[i][j]);
        }
        float bb[8];
        #pragma unroll
        for (int j = 0; j < 8; j++) bb[j] = __ldg(b_emb + n0 + j);
        #pragma unroll
        for (int j = 0; j < 8; j++) {
            float4 lo = {c[0][j] + bb[j], c[1][j] + bb[j],
                         c[2][j] + bb[j], c[3][j] + bb[j]};
            float4 hi = {c[4][j] + bb[j], c[5][j] + bb[j],
                         c[6][j] + bb[j], c[7][j] + bb[j]};
            *reinterpret_cast<float4*>(actA + (n0 + j) * LDA + m0)     = lo;
            *reinterpret_cast<float4*>(actA + (n0 + j) * LDA + m0 + 4) = hi;
        }
        __syncthreads();
    }

    // ---- Step 1 & 2 ------------------------------------------------------
    mlp128T(actA, actB, wb0, wb1, W1, b1, tid, m0, n0);
    mlp128T(actB, actA, wb0, wb1, W2, b2, tid, m0, n0);

    // ---- Step 3: Out = s @ Wc [128 x 288], sT in actA [k][m] -------------
    const int nc0 = tx * 6;
    #pragma unroll 1
    for (int c3 = 0; c3 < 3; c3++) {
        const int col0 = c3 * 96;
        float c[8][6] = {};
        float* cur = wb0;
        float* nxt = wb1;
        load_w96(cur, Wc, 0, col0, tid);
        __syncthreads();
        #pragma unroll 1
        for (int ch = 0; ch < 4; ch++) {
            if (ch < 3) load_w96(nxt, Wc, (ch + 1) * 32, col0, tid);
            const int kc = ch * 32;
            #pragma unroll 8
            for (int kk = 0; kk < 32; kk++) {
                float4 a0 = *reinterpret_cast<const float4*>(actA + (kc + kk) * LDA + m0);
                float4 a1 = *reinterpret_cast<const float4*>(actA + (kc + kk) * LDA + m0 + 4);
                float a[8] = {a0.x, a0.y, a0.z, a0.w, a1.x, a1.y, a1.z, a1.w};
                float w[6];
                #pragma unroll
                for (int j = 0; j < 6; j++) w[j] = cur[kk * LDA + nc0 + j];
                #pragma unroll
                for (int i = 0; i < 8; i++)
                    #pragma unroll
                    for (int j = 0; j < 6; j++)
                        c[i][j] = fmaf(a[i], w[j], c[i][j]);
            }
            __syncthreads();
            float* t = cur; cur = nxt; nxt = t;
        }
        #pragma unroll
        for (int i = 0; i < 8; i++) {
            float* op = Out + (size_t)(row0 + m0 + i) * H_ + col0 + nc0;
            #pragma unroll
            for (int j = 0; j < 6; j++) op[j] = c[i][j];
        }
    }
}

// ---------------------------------------------------------------------------
// pet_kernel
// ---------------------------------------------------------------------------
__global__ void pet_kernel(const float* __restrict__ Wc1,
                           const float* __restrict__ bc1)
{
    const int t = blockIdx.x;
    const int c = threadIdx.x;

    __shared__ float sv[4][8];
    if (c < 8) {
        int i = c;
        double dv = exp((double)(2 * i) * (-log(10000.0) / 16.0));
        double a1 = (double)(t + 1) * dv;
        double a0 = (double)t * dv;
        sv[0][i] = (float)sin(a1);
        sv[1][i] = (float)cos(a1);
        sv[2][i] = (float)sin(a0);
        sv[3][i] = (float)cos(a0);
    }
    __syncthreads();

    float acc = bc1[c];
    #pragma unroll
    for (int i = 0; i < 8; i++) {
        acc = fmaf(sv[0][i], Wc1[(128 + 2 * i) * H_ + c], acc);
        acc = fmaf(sv[1][i], Wc1[(129 + 2 * i) * H_ + c], acc);
        acc = fmaf(sv[2][i], Wc1[(272 + 2 * i) * H_ + c], acc);
        acc = fmaf(sv[3][i], Wc1[(273 + 2 * i) * H_ + c], acc);
    }
    g_pet[t * H_ + c] = acc;
}

// ---------------------------------------------------------------------------
// edge_kernel (unchanged)
// ---------------------------------------------------------------------------
__global__ __launch_bounds__(256)
void edge_kernel(const int* __restrict__ se, const int* __restrict__ re,
                 const float* __restrict__ Wc2, const float* __restrict__ bc2,
                 float* __restrict__ out)
{
    __shared__ float sS[128][33];
    __shared__ float sR[128][33];
    __shared__ float sW[H_ * 5];
    __shared__ float sPet[H_];

    const int t   = blockIdx.x;
    const int b   = blockIdx.y;
    const int tid = threadIdx.x;

    const float* Srow = g_S1 + (size_t)((b * T_ + t + 1) * N_) * H_;
    const float* Rrow = g_R1 + (size_t)((b * T_ + t) * N_) * H_;

    for (int l = tid; l < H_ * 5; l += 256) sW[l] = Wc2[l];
    for (int l = tid; l < H_;     l += 256) sPet[l] = g_pet[t * H_ + l];

    float bb[5];
    #pragma unroll
    for (int j = 0; j < 5; j++) bb[j] = __ldg(bc2 + j);

    int es[4], er[4];
    #pragma unroll
    for (int u = 0; u < 4; u++) {
        int e = u * 256 + tid;
        es[u] = __ldg(se + e);
        er[u] = __ldg(re + e);
    }
    float acc[4][5] = {};

    #pragma unroll 1
    for (int kc = 0; kc < H_; kc += 32) {
        __syncthreads();
        #pragma unroll
        for (int it = 0; it < 4; it++) {
            int l  = tid + it * 256;
            int n  = l >> 3;
            int k4 = (l & 7) * 4;
            float4 v = *reinterpret_cast<const float4*>(Srow + (size_t)n * H_ + kc + k4);
            sS[n][k4 + 0] = v.x; sS[n][k4 + 1] = v.y;
            sS[n][k4 + 2] = v.z; sS[n][k4 + 3] = v.w;
            float4 u4 = *reinterpret_cast<const float4*>(Rrow + (size_t)n * H_ + kc + k4);
            sR[n][k4 + 0] = u4.x; sR[n][k4 + 1] = u4.y;
            sR[n][k4 + 2] = u4.z; sR[n][k4 + 3] = u4.w;
        }
        __syncthreads();
        #pragma unroll
        for (int kk = 0; kk < 32; kk++) {
            float pv = sPet[kc + kk];
            float w0 = sW[(kc + kk) * 5 + 0];
            float w1 = sW[(kc + kk) * 5 + 1];
            float w2 = sW[(kc + kk) * 5 + 2];
            float w3 = sW[(kc + kk) * 5 + 3];
            float w4 = sW[(kc + kk) * 5 + 4];
            #pragma unroll
            for (int u = 0; u < 4; u++) {
                float h = sS[es[u]][kk] + sR[er[u]][kk] + pv;
                h = fmaxf(h, 0.f);
                acc[u][0] = fmaf(h, w0, acc[u][0]);
                acc[u][1] = fmaf(h, w1, acc[u][1]);
                acc[u][2] = fmaf(h, w2, acc[u][2]);
                acc[u][3] = fmaf(h, w3, acc[u][3]);
                acc[u][4] = fmaf(h, w4, acc[u][4]);
            }
        }
    }

    #pragma unroll
    for (int u = 0; u < 4; u++) {
        int e = u * 256 + tid;
        size_t o = ((size_t)(b * 255 + t) * E_ + e) * 5;
        #pragma unroll
        for (int j = 0; j < 5; j++) out[o + j] = acc[u][j] + bb[j];
    }
}

// ---------------------------------------------------------------------------
extern "C" void kernel_launch(void* const* d_in, const int* in_sizes, int n_in,
                              void* d_out, int out_size)
{
    const float* spikes = (const float*)d_in[0];
    const float* W_emb  = (const float*)d_in[1];
    const float* b_emb  = (const float*)d_in[2];
    const float* Ws1    = (const float*)d_in[3];
    const float* bs1    = (const float*)d_in[4];
    const float* Ws2    = (const float*)d_in[5];
    const float* bs2    = (const float*)d_in[6];
    const float* Wr1    = (const float*)d_in[7];
    const float* br1    = (const float*)d_in[8];
    const float* Wr2    = (const float*)d_in[9];
    const float* br2    = (const float*)d_in[10];
    const float* Wc1    = (const float*)d_in[11];
    const float* bc1    = (const float*)d_in[12];
    const float* Wc2    = (const float*)d_in[13];
    const float* bc2    = (const float*)d_in[14];
    const int*   se     = (const int*)d_in[15];
    const int*   re     = (const int*)d_in[16];
    float* out = (float*)d_out;

    cudaFuncSetAttribute(chain_kernel,
                         cudaFuncAttributeMaxDynamicSharedMemorySize,
                         (int)CHAIN_SMEM);

    chain_kernel<<<dim3(M_TOTAL / BM, 2), NTHREADS, CHAIN_SMEM>>>(
        spikes, W_emb, b_emb, Ws1, bs1, Ws2, bs2, Wr1, br1, Wr2, br2, Wc1);

    pet_kernel<<<255, H_>>>(Wc1, bc1);

    edge_kernel<<<dim3(255, 2), 256>>>(se, re, Wc2, bc2, out);
}

// round 7
// speedup vs baseline: 1.2318x; 1.0491x over previous
#include <cuda_runtime.h>
#include <cstdint>
#include <math.h>

// Problem dims
#define B_ 2
#define T_ 256
#define N_ 128
#define F_ 16
#define D_ 128
#define H_ 288
#define E_ 1024
#define M_TOTAL (B_*T_*N_)   // 65536 flattened node-time rows

// Chain kernel tiling
#define BM 128
#define LDA 132              // 128 + 4 pad
#define CHAIN_SMEM ((2*BM*LDA + 32*LDA) * sizeof(float))   // 152064 B

typedef unsigned long long u64;

// Scratch (static device arrays: allocation-free per harness rules)
__device__ float g_S1[(size_t)M_TOTAL * H_];   // send @ Wc1[0:128,:]
__device__ float g_R1[(size_t)M_TOTAL * H_];   // recv @ Wc1[144:272,:]
__device__ float g_pet[255 * H_];              // pe terms + bc1

// ---------------- f32x2 helpers (Blackwell packed fp32, base sm_100) -------
__device__ __forceinline__ u64 pack_ff(float x) {
    u64 r;
    asm("mov.b64 %0, {%1, %1};" : "=l"(r) : "f"(x));
    return r;
}
__device__ __forceinline__ void fma2(u64& d, u64 a, u64 b) {
    asm("fma.rn.f32x2 %0, %1, %2, %0;" : "+l"(d) : "l"(a), "l"(b));
}
__device__ __forceinline__ float2 unpack_ff(u64 v) {
    float2 f;
    asm("mov.b64 {%0, %1}, %2;" : "=f"(f.x), "=f"(f.y) : "l"(v));
    return f;
}

// ---------------------------------------------------------------------------
// mlp128: C = relu(A @ W + b), A,C are SMEM [128][LDA], W global [128][128]
// 256 threads, 8x8 per-thread tile computed as 8x(4 f32x2 pairs).
// ---------------------------------------------------------------------------
__device__ __forceinline__ void mlp128(const float* __restrict__ Asm,
                                       float* __restrict__ Csm,
                                       float* __restrict__ wbuf,
                                       const float* __restrict__ Wg,
                                       const float* __restrict__ bg,
                                       int tid, int m0, int n0)
{
    u64 cc[8][4] = {};
    #pragma unroll 1
    for (int kc = 0; kc < 128; kc += 32) {
        __syncthreads();
        #pragma unroll
        for (int it = 0; it < 4; it++) {
            int l  = tid + it * 256;          // 0..1023
            int kk = l >> 5;
            int c4 = (l & 31) * 4;
            float4 v = *reinterpret_cast<const float4*>(Wg + (size_t)(kc + kk) * 128 + c4);
            *reinterpret_cast<float4*>(wbuf + kk * LDA + c4) = v;
        }
        __syncthreads();
        #pragma unroll 8
        for (int kk = 0; kk < 32; kk++) {
            u64 ap[8];
            #pragma unroll
            for (int i = 0; i < 8; i++)
                ap[i] = pack_ff(Asm[(m0 + i) * LDA + kc + kk]);
            ulonglong2 w01 = *reinterpret_cast<const ulonglong2*>(wbuf + kk * LDA + n0);
            ulonglong2 w23 = *reinterpret_cast<const ulonglong2*>(wbuf + kk * LDA + n0 + 4);
            u64 wp0 = w01.x, wp1 = w01.y, wp2 = w23.x, wp3 = w23.y;
            #pragma unroll
            for (int i = 0; i < 8; i++) {
                fma2(cc[i][0], ap[i], wp0);
                fma2(cc[i][1], ap[i], wp1);
                fma2(cc[i][2], ap[i], wp2);
                fma2(cc[i][3], ap[i], wp3);
            }
        }
    }
    float bb[8];
    #pragma unroll
    for (int j = 0; j < 8; j++) bb[j] = __ldg(bg + n0 + j);
    #pragma unroll
    for (int i = 0; i < 8; i++) {
        float* cp = Csm + (m0 + i) * LDA + n0;
        #pragma unroll
        for (int jp = 0; jp < 4; jp++) {
            float2 v = unpack_ff(cc[i][jp]);
            cp[2*jp]     = fmaxf(v.x + bb[2*jp],     0.f);
            cp[2*jp + 1] = fmaxf(v.y + bb[2*jp + 1], 0.f);
        }
    }
}

// ---------------------------------------------------------------------------
// chain_kernel: per 128-row tile, fused
//   emb = spikes@W_emb + b_emb
//   h1  = relu(emb@W1 + b1)
//   s   = relu(h1@W2 + b2)
//   Out = s @ Wc1_sub (bc1 folded into g_pet)
// blockIdx.y: 0 = send chain -> g_S1, 1 = recv chain -> g_R1
// ---------------------------------------------------------------------------
__global__ __launch_bounds__(256, 1)
void chain_kernel(const float* __restrict__ spikes,
                  const float* __restrict__ W_emb, const float* __restrict__ b_emb,
                  const float* __restrict__ Ws1, const float* __restrict__ bs1,
                  const float* __restrict__ Ws2, const float* __restrict__ bs2,
                  const float* __restrict__ Wr1, const float* __restrict__ br1,
                  const float* __restrict__ Wr2, const float* __restrict__ br2,
                  const float* __restrict__ Wc1)
{
    extern __shared__ float sm[];
    float* actA = sm;                       // [BM][LDA]
    float* actB = sm + BM * LDA;            // [BM][LDA]
    float* wbuf = sm + 2 * BM * LDA;        // [32][LDA]

    const int chain = blockIdx.y;
    const float* W1 = chain ? Wr1 : Ws1;
    const float* b1 = chain ? br1 : bs1;
    const float* W2 = chain ? Wr2 : Ws2;
    const float* b2 = chain ? br2 : bs2;
    const float* Wc = Wc1 + (chain ? 144 * H_ : 0);
    float* Out = chain ? g_R1 : g_S1;

    const int row0 = blockIdx.x * BM;
    const int tid  = threadIdx.x;
    const int tx   = tid & 15;
    const int ty   = tid >> 4;
    const int m0   = ty * 8;
    const int n0   = tx * 8;

    // ---- Step 0: emb = spikes @ W_emb + b_emb -> actA -------------------
    // spikes^T staged at wbuf[k][m] (k<16), W_emb at wbuf[16+k][n]
    {
        #pragma unroll
        for (int it = 0; it < 2; it++) {
            int l = tid * 2 + it;           // 0..511
            int m = l >> 2;
            int q = l & 3;
            float4 v = *reinterpret_cast<const float4*>(
                spikes + (size_t)(row0 + m) * F_ + q * 4);
            wbuf[(q * 4 + 0) * LDA + m] = v.x;
            wbuf[(q * 4 + 1) * LDA + m] = v.y;
            wbuf[(q * 4 + 2) * LDA + m] = v.z;
            wbuf[(q * 4 + 3) * LDA + m] = v.w;
        }
        #pragma unroll
        for (int it = 0; it < 2; it++) {
            int l  = tid * 2 + it;          // 0..511
            int k  = l >> 5;
            int c4 = (l & 31) * 4;
            float4 v = *reinterpret_cast<const float4*>(W_emb + k * 128 + c4);
            *reinterpret_cast<float4*>(wbuf + (16 + k) * LDA + c4) = v;
        }
        __syncthreads();

        u64 cc[8][4] = {};
        #pragma unroll
        for (int k = 0; k < 16; k++) {
            u64 ap[8];
            #pragma unroll
            for (int i = 0; i < 8; i++)
                ap[i] = pack_ff(wbuf[k * LDA + m0 + i]);
            ulonglong2 w01 = *reinterpret_cast<const ulonglong2*>(wbuf + (16 + k) * LDA + n0);
            ulonglong2 w23 = *reinterpret_cast<const ulonglong2*>(wbuf + (16 + k) * LDA + n0 + 4);
            u64 wp0 = w01.x, wp1 = w01.y, wp2 = w23.x, wp3 = w23.y;
            #pragma unroll
            for (int i = 0; i < 8; i++) {
                fma2(cc[i][0], ap[i], wp0);
                fma2(cc[i][1], ap[i], wp1);
                fma2(cc[i][2], ap[i], wp2);
                fma2(cc[i][3], ap[i], wp3);
            }
        }
        float bb[8];
        #pragma unroll
        for (int j = 0; j < 8; j++) bb[j] = __ldg(b_emb + n0 + j);
        #pragma unroll
        for (int i = 0; i < 8; i++) {
            float* cp = actA + (m0 + i) * LDA + n0;
            #pragma unroll
            for (int jp = 0; jp < 4; jp++) {
                float2 v = unpack_ff(cc[i][jp]);
                cp[2*jp]     = v.x + bb[2*jp];
                cp[2*jp + 1] = v.y + bb[2*jp + 1];
            }
        }
        // no trailing sync: mlp128's first chunk sync covers visibility
    }

    // ---- Step 1: h1 = relu(emb @ W1 + b1) -> actB -----------------------
    mlp128(actA, actB, wbuf, W1, b1, tid, m0, n0);
    // ---- Step 2: s = relu(h1 @ W2 + b2) -> actA -------------------------
    mlp128(actB, actA, wbuf, W2, b2, tid, m0, n0);

    // ---- Step 3: Out = s @ Wc [128 x 288], 3 column chunks of 96 --------
    const int nc0 = tx * 6;
    #pragma unroll 1
    for (int c3 = 0; c3 < 3; c3++) {
        const int col0 = c3 * 96;
        u64 cc[8][3] = {};
        #pragma unroll 1
        for (int kc = 0; kc < 128; kc += 32) {
            __syncthreads();
            #pragma unroll
            for (int it = 0; it < 3; it++) {
                int l  = tid + it * 256;    // 0..767
                int kk = l / 24;
                int c4 = (l % 24) * 4;
                float4 v = *reinterpret_cast<const float4*>(
                    Wc + (size_t)(kc + kk) * H_ + col0 + c4);
                *reinterpret_cast<float4*>(wbuf + kk * LDA + c4) = v;
            }
            __syncthreads();
            #pragma unroll 8
            for (int kk = 0; kk < 32; kk++) {
                u64 ap[8];
                #pragma unroll
                for (int i = 0; i < 8; i++)
                    ap[i] = pack_ff(actA[(m0 + i) * LDA + kc + kk]);
                const float* wr = wbuf + kk * LDA + nc0;   // nc0 even -> 8B aligned
                u64 wp0 = *reinterpret_cast<const u64*>(wr);
                u64 wp1 = *reinterpret_cast<const u64*>(wr + 2);
                u64 wp2 = *reinterpret_cast<const u64*>(wr + 4);
                #pragma unroll
                for (int i = 0; i < 8; i++) {
                    fma2(cc[i][0], ap[i], wp0);
                    fma2(cc[i][1], ap[i], wp1);
                    fma2(cc[i][2], ap[i], wp2);
                }
            }
        }
        #pragma unroll
        for (int i = 0; i < 8; i++) {
            float* op = Out + (size_t)(row0 + m0 + i) * H_ + col0 + nc0;
            #pragma unroll
            for (int jp = 0; jp < 3; jp++) {
                float2 v = unpack_ff(cc[i][jp]);
                op[2*jp]     = v.x;
                op[2*jp + 1] = v.y;
            }
        }
    }
}

// ---------------------------------------------------------------------------
// pet_kernel: pet[t][c] = pe[t+1] @ Wc1[128:144,c] + pe[t] @ Wc1[272:288,c] + bc1[c]
// ---------------------------------------------------------------------------
__global__ void pet_kernel(const float* __restrict__ Wc1,
                           const float* __restrict__ bc1)
{
    const int t = blockIdx.x;       // 0..254
    const int c = threadIdx.x;      // 0..287

    __shared__ float sv[4][8];
    if (c < 8) {
        int i = c;
        double dv = exp((double)(2 * i) * (-log(10000.0) / 16.0));
        double a1 = (double)(t + 1) * dv;
        double a0 = (double)t * dv;
        sv[0][i] = (float)sin(a1);
        sv[1][i] = (float)cos(a1);
        sv[2][i] = (float)sin(a0);
        sv[3][i] = (float)cos(a0);
    }
    __syncthreads();

    float acc = bc1[c];
    #pragma unroll
    for (int i = 0; i < 8; i++) {
        acc = fmaf(sv[0][i], Wc1[(128 + 2 * i) * H_ + c], acc);
        acc = fmaf(sv[1][i], Wc1[(129 + 2 * i) * H_ + c], acc);
        acc = fmaf(sv[2][i], Wc1[(272 + 2 * i) * H_ + c], acc);
        acc = fmaf(sv[3][i], Wc1[(273 + 2 * i) * H_ + c], acc);
    }
    g_pet[t * H_ + c] = acc;
}

// ---------------------------------------------------------------------------
// edge_kernel: per (b,t) block:
//   h[e,k] = relu(S1[b,t+1,se[e],k] + R1[b,t,re[e],k] + pet[t,k])
//   out[b,t,e,:] = h[e,:] @ Wc2 + bc2
// ---------------------------------------------------------------------------
__global__ __launch_bounds__(256)
void edge_kernel(const int* __restrict__ se, const int* __restrict__ re,
                 const float* __restrict__ Wc2, const float* __restrict__ bc2,
                 float* __restrict__ out)
{
    __shared__ float sS[128][33];
    __shared__ float sR[128][33];
    __shared__ float sW[H_ * 5];
    __shared__ float sPet[H_];

    const int t   = blockIdx.x;     // 0..254
    const int b   = blockIdx.y;     // 0..1
    const int tid = threadIdx.x;

    const float* Srow = g_S1 + (size_t)((b * T_ + t + 1) * N_) * H_;
    const float* Rrow = g_R1 + (size_t)((b * T_ + t) * N_) * H_;

    for (int l = tid; l < H_ * 5; l += 256) sW[l] = Wc2[l];
    for (int l = tid; l < H_;     l += 256) sPet[l] = g_pet[t * H_ + l];

    float bb[5];
    #pragma unroll
    for (int j = 0; j < 5; j++) bb[j] = __ldg(bc2 + j);

    int es[4], er[4];
    #pragma unroll
    for (int u = 0; u < 4; u++) {
        int e = u * 256 + tid;
        es[u] = __ldg(se + e);
        er[u] = __ldg(re + e);
    }
    float acc[4][5] = {};

    #pragma unroll 1
    for (int kc = 0; kc < H_; kc += 32) {
        __syncthreads();
        #pragma unroll
        for (int it = 0; it < 4; it++) {
            int l  = tid + it * 256;     // 0..1023
            int n  = l >> 3;
            int k4 = (l & 7) * 4;
            float4 v = *reinterpret_cast<const float4*>(Srow + (size_t)n * H_ + kc + k4);
            sS[n][k4 + 0] = v.x; sS[n][k4 + 1] = v.y;
            sS[n][k4 + 2] = v.z; sS[n][k4 + 3] = v.w;
            float4 u4 = *reinterpret_cast<const float4*>(Rrow + (size_t)n * H_ + kc + k4);
            sR[n][k4 + 0] = u4.x; sR[n][k4 + 1] = u4.y;
            sR[n][k4 + 2] = u4.z; sR[n][k4 + 3] = u4.w;
        }
        __syncthreads();
        #pragma unroll
        for (int kk = 0; kk < 32; kk++) {
            float pv = sPet[kc + kk];
            float w0 = sW[(kc + kk) * 5 + 0];
            float w1 = sW[(kc + kk) * 5 + 1];
            float w2 = sW[(kc + kk) * 5 + 2];
            float w3 = sW[(kc + kk) * 5 + 3];
            float w4 = sW[(kc + kk) * 5 + 4];
            #pragma unroll
            for (int u = 0; u < 4; u++) {
                float h = sS[es[u]][kk] + sR[er[u]][kk] + pv;
                h = fmaxf(h, 0.f);
                acc[u][0] = fmaf(h, w0, acc[u][0]);
                acc[u][1] = fmaf(h, w1, acc[u][1]);
                acc[u][2] = fmaf(h, w2, acc[u][2]);
                acc[u][3] = fmaf(h, w3, acc[u][3]);
                acc[u][4] = fmaf(h, w4, acc[u][4]);
            }
        }
    }

    #pragma unroll
    for (int u = 0; u < 4; u++) {
        int e = u * 256 + tid;
        size_t o = ((size_t)(b * 255 + t) * E_ + e) * 5;
        #pragma unroll
        for (int j = 0; j < 5; j++) out[o + j] = acc[u][j] + bb[j];
    }
}

// ---------------------------------------------------------------------------
extern "C" void kernel_launch(void* const* d_in, const int* in_sizes, int n_in,
                              void* d_out, int out_size)
{
    const float* spikes = (const float*)d_in[0];
    const float* W_emb  = (const float*)d_in[1];
    const float* b_emb  = (const float*)d_in[2];
    const float* Ws1    = (const float*)d_in[3];
    const float* bs1    = (const float*)d_in[4];
    const float* Ws2    = (const float*)d_in[5];
    const float* bs2    = (const float*)d_in[6];
    const float* Wr1    = (const float*)d_in[7];
    const float* br1    = (const float*)d_in[8];
    const float* Wr2    = (const float*)d_in[9];
    const float* br2    = (const float*)d_in[10];
    const float* Wc1    = (const float*)d_in[11];
    const float* bc1    = (const float*)d_in[12];
    const float* Wc2    = (const float*)d_in[13];
    const float* bc2    = (const float*)d_in[14];
    const int*   se     = (const int*)d_in[15];
    const int*   re     = (const int*)d_in[16];
    float* out = (float*)d_out;

    cudaFuncSetAttribute(chain_kernel,
                         cudaFuncAttributeMaxDynamicSharedMemorySize,
                         (int)CHAIN_SMEM);

    chain_kernel<<<dim3(M_TOTAL / BM, 2), 256, CHAIN_SMEM>>>(
        spikes, W_emb, b_emb, Ws1, bs1, Ws2, bs2, Wr1, br1, Wr2, br2, Wc1);

    pet_kernel<<<255, H_>>>(Wc1, bc1);

    edge_kernel<<<dim3(255, 2), 256>>>(se, re, Wc2, bc2, out);
}